// round 11
// baseline (speedup 1.0000x reference)
#include <cuda_runtime.h>
#include <cuda_bf16.h>

#define HH 512
#define WW 512
#define HWN (HH * WW)           // 262144 = 1<<18
#define NB 8
#define NC 16

// Scratch: scatter-winner per target pixel (largest source pixel index wins,
// matching sequential last-write-wins of the reference scatter).
__device__ int   g_winner[NB * HWN];
__device__ float g_M[NB][9];

// ---------------------------------------------------------------------------
// M[b] = (K @ R[b]) @ Kinv  (association A). k-ascending FMA chains.
// DO NOT TOUCH: this exact chain produced rel_err == 0.0.
// ---------------------------------------------------------------------------
__global__ void compute_M_kernel(const float* __restrict__ R,
                                 const float* __restrict__ K,
                                 const float* __restrict__ Kinv) {
    int b = threadIdx.x;
    if (b >= NB) return;
    const float* Rb = R + b * 9;
    float KR[9];
#pragma unroll
    for (int i = 0; i < 3; i++) {
#pragma unroll
        for (int k = 0; k < 3; k++) {
            float s = __fmul_rn(K[i * 3 + 0], Rb[0 * 3 + k]);
            s = __fmaf_rn(K[i * 3 + 1], Rb[1 * 3 + k], s);
            s = __fmaf_rn(K[i * 3 + 2], Rb[2 * 3 + k], s);
            KR[i * 3 + k] = s;
        }
    }
#pragma unroll
    for (int i = 0; i < 3; i++) {
#pragma unroll
        for (int j = 0; j < 3; j++) {
            float s = __fmul_rn(KR[i * 3 + 0], Kinv[0 * 3 + j]);
            s = __fmaf_rn(KR[i * 3 + 1], Kinv[1 * 3 + j], s);
            s = __fmaf_rn(KR[i * 3 + 2], Kinv[2 * 3 + j], s);
            g_M[b][i * 3 + j] = s;
        }
    }
}

// ---------------------------------------------------------------------------
// Winner init: -1 everywhere (vectorized int4 stores)
// ---------------------------------------------------------------------------
__global__ void init_winner_kernel() {
    int i = blockIdx.x * blockDim.x + threadIdx.x;
    ((int4*)g_winner)[i] = make_int4(-1, -1, -1, -1);
}

// ---------------------------------------------------------------------------
// Projection + scatter. DO NOT TOUCH the arithmetic: rel_err == 0.0 with
// frcp_rn-based divide rewrites + gemm FMA x-chain + single-add t.
// ---------------------------------------------------------------------------
__global__ void scatter_kernel(const float* __restrict__ depth,
                               const float* __restrict__ T,
                               const float* __restrict__ K) {
    int idx = blockIdx.x * blockDim.x + threadIdx.x;   // 0 .. NB*HWN-1
    int b = idx >> 18;
    int p = idx & (HWN - 1);
    float gx = (float)(p >> 9);
    float gy = (float)(p & 511);

    float d = fmaxf(depth[idx], 0.1f);

    float rd = __frcp_rn(d);
    float v0 = __fmul_rn(T[b * 3 + 0], rd);
    float v1 = __fmul_rn(T[b * 3 + 1], rd);
    float v2 = __fmul_rn(T[b * 3 + 2], rd);

    const float* M = g_M[b];
    float x0 = __fadd_rn(__fmaf_rn(M[1], gy, __fmul_rn(M[0], gx)), M[2]);
    float x1 = __fadd_rn(__fmaf_rn(M[4], gy, __fmul_rn(M[3], gx)), M[5]);
    float x2 = __fadd_rn(__fmaf_rn(M[7], gy, __fmul_rn(M[6], gx)), M[8]);

    float y0 = __fmaf_rn(K[2], v2, __fmaf_rn(K[1], v1, __fmul_rn(K[0], v0)));
    float y1 = __fmaf_rn(K[5], v2, __fmaf_rn(K[4], v1, __fmul_rn(K[3], v0)));
    float y2 = __fmaf_rn(K[8], v2, __fmaf_rn(K[7], v1, __fmul_rn(K[6], v0)));

    float t0 = __fadd_rn(x0, y0);
    float t1 = __fadd_rn(x1, y1);
    float t2 = __fadd_rn(x2, y2);

    if (t0 == 0.0f) t0 = 1e-4f;
    if (t1 == 0.0f) t1 = 1e-4f;
    if (t2 == 0.0f) t2 = 1e-4f;

    float rt2 = __frcp_rn(t2);
    float u = __fmul_rn(t0, rt2);
    float v = __fmul_rn(t1, rt2);
    u = fminf(fmaxf(u, 0.0f), 511.0f);
    v = fminf(fmaxf(v, 0.0f), 511.0f);

    int q = ((int)u << 9) + (int)v;
    atomicMax(&g_winner[(b << 18) + q], p);
}

// ---------------------------------------------------------------------------
// Gather + maxpool(2x2) + nearest upsample(x2), fused.
// Block = 256 threads: one pooled tile (4 rows x 64 cols) x 4 channels.
// Single burst of 16 outstanding gathers per thread; ~32 regs so 8 blocks/SM
// (full occupancy). Winner tile staged via one int4 load per thread.
// ---------------------------------------------------------------------------
__global__ void __launch_bounds__(256) gather_pool_kernel(
        const float* __restrict__ image, float* __restrict__ out) {
    int blk   = blockIdx.x;
    int quad  = blk & 3;             // channel quarter: c = quad*4 .. quad*4+3
    int tile  = (blk >> 2) & 255;    // 256 tiles per image
    int b     = blk >> 10;
    int i0 = (tile >> 2) * 4;        // pooled-row start (0..252)
    int j0 = (tile & 3) * 64;        // pooled-col start (0..192)

    __shared__ int sw[8][128];

    int tid = threadIdx.x;
    // stage 8x128 winner tile: one int4 per thread (rows of 128 ints = 32 int4)
    {
        int r  = tid >> 5;           // 0..7
        int c4 = tid & 31;           // 0..31
        const int4* wrow = (const int4*)(g_winner + (b << 18) + (2 * i0 + r) * WW + 2 * j0);
        *(int4*)&sw[r][c4 * 4] = wrow[c4];
    }
    __syncthreads();

    int li = tid >> 6;                    // 0..3  pooled row within tile
    int jj = tid & 63;                    // 0..63 pooled col within tile
    int w00 = sw[2 * li][2 * jj];
    int w01 = sw[2 * li][2 * jj + 1];
    int w10 = sw[2 * li + 1][2 * jj];
    int w11 = sw[2 * li + 1][2 * jj + 1];

    // clamped addresses (branchless); validity masks applied post-load
    int a00 = max(w00, 0), a01 = max(w01, 0);
    int a10 = max(w10, 0), a11 = max(w11, 0);

    int i2 = i0 + li;
    int j2 = j0 + jj;
    int opix = (2 * i2) * WW + 2 * j2;

    int cbase = b * NC + quad * 4;
    float v[16];
#pragma unroll
    for (int c = 0; c < 4; c++) {
        const float* img = image + ((unsigned)(cbase + c) << 18);
        v[c * 4 + 0] = __ldg(img + a00);
        v[c * 4 + 1] = __ldg(img + a01);
        v[c * 4 + 2] = __ldg(img + a10);
        v[c * 4 + 3] = __ldg(img + a11);
    }
#pragma unroll
    for (int c = 0; c < 4; c++) {
        float b0 = (w00 >= 0) ? v[c * 4 + 0] : 0.0f;
        float b1 = (w01 >= 0) ? v[c * 4 + 1] : 0.0f;
        float b2 = (w10 >= 0) ? v[c * 4 + 2] : 0.0f;
        float b3 = (w11 >= 0) ? v[c * 4 + 3] : 0.0f;
        float m = fmaxf(fmaxf(b0, b1), fmaxf(b2, b3));

        float* o = out + ((unsigned)(cbase + c) << 18) + opix;
        float2 vv = make_float2(m, m);
        *(float2*)(o)      = vv;
        *(float2*)(o + WW) = vv;
    }
}

// ---------------------------------------------------------------------------
extern "C" void kernel_launch(void* const* d_in, const int* in_sizes, int n_in,
                              void* d_out, int out_size) {
    const float* image = (const float*)d_in[0];   // [8,16,512,512]
    const float* depth = (const float*)d_in[1];   // [8,512,512]
    const float* T     = (const float*)d_in[2];   // [8,3,1]
    const float* R     = (const float*)d_in[3];   // [8,3,3]
    const float* K     = (const float*)d_in[4];   // [3,3]
    const float* Kinv  = (const float*)d_in[5];   // [3,3]
    float* out = (float*)d_out;

    compute_M_kernel<<<1, 32>>>(R, K, Kinv);
    init_winner_kernel<<<(NB * HWN / 4) / 256, 256>>>();
    scatter_kernel<<<(NB * HWN) / 256, 256>>>(depth, T, K);
    gather_pool_kernel<<<NB * 1024, 256>>>(image, out);
}

// round 12
// speedup vs baseline: 1.0252x; 1.0252x over previous
#include <cuda_runtime.h>
#include <cuda_bf16.h>

#define HH 512
#define WW 512
#define HWN (HH * WW)           // 262144 = 1<<18
#define NB 8
#define NC 16

// Scratch: scatter-winner per target pixel (largest source pixel index wins,
// matching sequential last-write-wins of the reference scatter).
__device__ int   g_winner[NB * HWN];
__device__ float g_M[NB][9];

// ---------------------------------------------------------------------------
// M[b] = (K @ R[b]) @ Kinv  (association A). k-ascending FMA chains.
// DO NOT TOUCH: this exact chain produced rel_err == 0.0.
// ---------------------------------------------------------------------------
__global__ void compute_M_kernel(const float* __restrict__ R,
                                 const float* __restrict__ K,
                                 const float* __restrict__ Kinv) {
    int b = threadIdx.x;
    if (b >= NB) return;
    const float* Rb = R + b * 9;
    float KR[9];
#pragma unroll
    for (int i = 0; i < 3; i++) {
#pragma unroll
        for (int k = 0; k < 3; k++) {
            float s = __fmul_rn(K[i * 3 + 0], Rb[0 * 3 + k]);
            s = __fmaf_rn(K[i * 3 + 1], Rb[1 * 3 + k], s);
            s = __fmaf_rn(K[i * 3 + 2], Rb[2 * 3 + k], s);
            KR[i * 3 + k] = s;
        }
    }
#pragma unroll
    for (int i = 0; i < 3; i++) {
#pragma unroll
        for (int j = 0; j < 3; j++) {
            float s = __fmul_rn(KR[i * 3 + 0], Kinv[0 * 3 + j]);
            s = __fmaf_rn(KR[i * 3 + 1], Kinv[1 * 3 + j], s);
            s = __fmaf_rn(KR[i * 3 + 2], Kinv[2 * 3 + j], s);
            g_M[b][i * 3 + j] = s;
        }
    }
}

// ---------------------------------------------------------------------------
// Winner init: -1 everywhere (vectorized int4 stores)
// ---------------------------------------------------------------------------
__global__ void init_winner_kernel() {
    int i = blockIdx.x * blockDim.x + threadIdx.x;
    ((int4*)g_winner)[i] = make_int4(-1, -1, -1, -1);
}

// ---------------------------------------------------------------------------
// Projection + scatter. DO NOT TOUCH the arithmetic: rel_err == 0.0 with
// frcp_rn-based divide rewrites + gemm FMA x-chain + single-add t.
// ---------------------------------------------------------------------------
__global__ void scatter_kernel(const float* __restrict__ depth,
                               const float* __restrict__ T,
                               const float* __restrict__ K) {
    int idx = blockIdx.x * blockDim.x + threadIdx.x;   // 0 .. NB*HWN-1
    int b = idx >> 18;
    int p = idx & (HWN - 1);
    float gx = (float)(p >> 9);
    float gy = (float)(p & 511);

    float d = fmaxf(depth[idx], 0.1f);

    float rd = __frcp_rn(d);
    float v0 = __fmul_rn(T[b * 3 + 0], rd);
    float v1 = __fmul_rn(T[b * 3 + 1], rd);
    float v2 = __fmul_rn(T[b * 3 + 2], rd);

    const float* M = g_M[b];
    float x0 = __fadd_rn(__fmaf_rn(M[1], gy, __fmul_rn(M[0], gx)), M[2]);
    float x1 = __fadd_rn(__fmaf_rn(M[4], gy, __fmul_rn(M[3], gx)), M[5]);
    float x2 = __fadd_rn(__fmaf_rn(M[7], gy, __fmul_rn(M[6], gx)), M[8]);

    float y0 = __fmaf_rn(K[2], v2, __fmaf_rn(K[1], v1, __fmul_rn(K[0], v0)));
    float y1 = __fmaf_rn(K[5], v2, __fmaf_rn(K[4], v1, __fmul_rn(K[3], v0)));
    float y2 = __fmaf_rn(K[8], v2, __fmaf_rn(K[7], v1, __fmul_rn(K[6], v0)));

    float t0 = __fadd_rn(x0, y0);
    float t1 = __fadd_rn(x1, y1);
    float t2 = __fadd_rn(x2, y2);

    if (t0 == 0.0f) t0 = 1e-4f;
    if (t1 == 0.0f) t1 = 1e-4f;
    if (t2 == 0.0f) t2 = 1e-4f;

    float rt2 = __frcp_rn(t2);
    float u = __fmul_rn(t0, rt2);
    float v = __fmul_rn(t1, rt2);
    u = fminf(fmaxf(u, 0.0f), 511.0f);
    v = fminf(fmaxf(v, 0.0f), 511.0f);

    int q = ((int)u << 9) + (int)v;
    atomicMax(&g_winner[(b << 18) + q], p);
}

// ---------------------------------------------------------------------------
// Gather + maxpool(2x2) + nearest upsample(x2), fused.  [R7 structure]
// Block = 256 threads: one pooled tile (4 rows x 64 cols) x 8 channels.
// Two bursts of 16 outstanding gathers per thread. int4 winner staging,
// streaming (evict-first) output stores.
// ---------------------------------------------------------------------------
__global__ void __launch_bounds__(256) gather_pool_kernel(
        const float* __restrict__ image, float* __restrict__ out) {
    int blk  = blockIdx.x;
    int half = blk & 1;              // channel half: 0 -> c0..7, 1 -> c8..15
    int tile = (blk >> 1) & 255;     // 256 tiles per image
    int b    = blk >> 9;
    int i0 = (tile >> 2) * 4;        // pooled-row start (0..252)
    int j0 = (tile & 3) * 64;        // pooled-col start (0..192)

    __shared__ int sw[8][128];

    int tid = threadIdx.x;
    // stage 8x128 winner tile: one int4 per thread (8 rows x 32 int4)
    {
        int r  = tid >> 5;           // 0..7
        int c4 = tid & 31;           // 0..31
        const int4* wrow = (const int4*)(g_winner + (b << 18) + (2 * i0 + r) * WW + 2 * j0);
        *(int4*)&sw[r][c4 * 4] = wrow[c4];
    }
    __syncthreads();

    int li = tid >> 6;                    // 0..3  pooled row within tile
    int jj = tid & 63;                    // 0..63 pooled col within tile
    int w00 = sw[2 * li][2 * jj];
    int w01 = sw[2 * li][2 * jj + 1];
    int w10 = sw[2 * li + 1][2 * jj];
    int w11 = sw[2 * li + 1][2 * jj + 1];

    // clamped addresses (branchless); validity masks applied post-load
    int a00 = max(w00, 0), a01 = max(w01, 0);
    int a10 = max(w10, 0), a11 = max(w11, 0);

    int i2 = i0 + li;
    int j2 = j0 + jj;
    int opix = (2 * i2) * WW + 2 * j2;

    int cbase = half * 8;
#pragma unroll
    for (int cc = 0; cc < 8; cc += 4) {
        float v[16];
#pragma unroll
        for (int c = 0; c < 4; c++) {
            const float* img = image + ((unsigned)((b * NC + cbase + cc + c)) << 18);
            v[c * 4 + 0] = __ldg(img + a00);
            v[c * 4 + 1] = __ldg(img + a01);
            v[c * 4 + 2] = __ldg(img + a10);
            v[c * 4 + 3] = __ldg(img + a11);
        }
#pragma unroll
        for (int c = 0; c < 4; c++) {
            float b0 = (w00 >= 0) ? v[c * 4 + 0] : 0.0f;
            float b1 = (w01 >= 0) ? v[c * 4 + 1] : 0.0f;
            float b2 = (w10 >= 0) ? v[c * 4 + 2] : 0.0f;
            float b3 = (w11 >= 0) ? v[c * 4 + 3] : 0.0f;
            float m = fmaxf(fmaxf(b0, b1), fmaxf(b2, b3));

            float* o = out + ((unsigned)((b * NC + cbase + cc + c)) << 18) + opix;
            float2 vv = make_float2(m, m);
            __stcs((float2*)(o), vv);
            __stcs((float2*)(o + WW), vv);
        }
    }
}

// ---------------------------------------------------------------------------
extern "C" void kernel_launch(void* const* d_in, const int* in_sizes, int n_in,
                              void* d_out, int out_size) {
    const float* image = (const float*)d_in[0];   // [8,16,512,512]
    const float* depth = (const float*)d_in[1];   // [8,512,512]
    const float* T     = (const float*)d_in[2];   // [8,3,1]
    const float* R     = (const float*)d_in[3];   // [8,3,3]
    const float* K     = (const float*)d_in[4];   // [3,3]
    const float* Kinv  = (const float*)d_in[5];   // [3,3]
    float* out = (float*)d_out;

    compute_M_kernel<<<1, 32>>>(R, K, Kinv);
    init_winner_kernel<<<(NB * HWN / 4) / 256, 256>>>();
    scatter_kernel<<<(NB * HWN) / 256, 256>>>(depth, T, K);
    gather_pool_kernel<<<NB * 512, 256>>>(image, out);
}

// round 14
// speedup vs baseline: 1.0419x; 1.0163x over previous
#include <cuda_runtime.h>
#include <cuda_bf16.h>

#define HH 512
#define WW 512
#define HWN (HH * WW)           // 262144 = 1<<18
#define NB 8
#define NC 16

// Scratch: scatter-winner per target pixel (largest source pixel index wins,
// matching sequential last-write-wins of the reference scatter).
__device__ int g_winner[NB * HWN];

// ---------------------------------------------------------------------------
// Projection + scatter, with M = (K @ R[b]) @ Kinv computed per block
// (thread 0, exact frozen chain -> smem). DO NOT TOUCH the arithmetic:
// rel_err == 0.0 with frcp_rn divide rewrites + gemm FMA x-chain + single-add.
// ---------------------------------------------------------------------------
__global__ void __launch_bounds__(256) scatter_kernel(
        const float* __restrict__ depth,
        const float* __restrict__ T,
        const float* __restrict__ R,
        const float* __restrict__ K,
        const float* __restrict__ Kinv) {
    __shared__ float sM[9];
    int idx = blockIdx.x * 256 + threadIdx.x;    // 0 .. NB*HWN-1
    int b = idx >> 18;
    int p = idx & (HWN - 1);

    if (threadIdx.x == 0) {
        const float* Rb = R + b * 9;
        float KR[9];
#pragma unroll
        for (int i = 0; i < 3; i++) {
#pragma unroll
            for (int k = 0; k < 3; k++) {
                float s = __fmul_rn(K[i * 3 + 0], Rb[0 * 3 + k]);
                s = __fmaf_rn(K[i * 3 + 1], Rb[1 * 3 + k], s);
                s = __fmaf_rn(K[i * 3 + 2], Rb[2 * 3 + k], s);
                KR[i * 3 + k] = s;
            }
        }
#pragma unroll
        for (int i = 0; i < 3; i++) {
#pragma unroll
            for (int j = 0; j < 3; j++) {
                float s = __fmul_rn(KR[i * 3 + 0], Kinv[0 * 3 + j]);
                s = __fmaf_rn(KR[i * 3 + 1], Kinv[1 * 3 + j], s);
                s = __fmaf_rn(KR[i * 3 + 2], Kinv[2 * 3 + j], s);
                sM[i * 3 + j] = s;
            }
        }
    }
    __syncthreads();

    float gx = (float)(p >> 9);
    float gy = (float)(p & 511);

    float d = fmaxf(depth[idx], 0.1f);

    float rd = __frcp_rn(d);
    float v0 = __fmul_rn(T[b * 3 + 0], rd);
    float v1 = __fmul_rn(T[b * 3 + 1], rd);
    float v2 = __fmul_rn(T[b * 3 + 2], rd);

    const float* M = sM;
    float x0 = __fadd_rn(__fmaf_rn(M[1], gy, __fmul_rn(M[0], gx)), M[2]);
    float x1 = __fadd_rn(__fmaf_rn(M[4], gy, __fmul_rn(M[3], gx)), M[5]);
    float x2 = __fadd_rn(__fmaf_rn(M[7], gy, __fmul_rn(M[6], gx)), M[8]);

    float y0 = __fmaf_rn(K[2], v2, __fmaf_rn(K[1], v1, __fmul_rn(K[0], v0)));
    float y1 = __fmaf_rn(K[5], v2, __fmaf_rn(K[4], v1, __fmul_rn(K[3], v0)));
    float y2 = __fmaf_rn(K[8], v2, __fmaf_rn(K[7], v1, __fmul_rn(K[6], v0)));

    float t0 = __fadd_rn(x0, y0);
    float t1 = __fadd_rn(x1, y1);
    float t2 = __fadd_rn(x2, y2);

    if (t0 == 0.0f) t0 = 1e-4f;
    if (t1 == 0.0f) t1 = 1e-4f;
    if (t2 == 0.0f) t2 = 1e-4f;

    float rt2 = __frcp_rn(t2);
    float u = __fmul_rn(t0, rt2);
    float v = __fmul_rn(t1, rt2);
    u = fminf(fmaxf(u, 0.0f), 511.0f);
    v = fminf(fmaxf(v, 0.0f), 511.0f);

    int q = ((int)u << 9) + (int)v;
    atomicMax(&g_winner[(b << 18) + q], p);
}

// ---------------------------------------------------------------------------
// Gather + maxpool(2x2) + nearest upsample(x2), fused.  [R12 structure]
// Block = 256 threads: one pooled tile (4 rows x 64 cols) x 8 channels.
// Two bursts of 16 outstanding gathers per thread. int4 winner staging,
// streaming (evict-first) output stores.
// ---------------------------------------------------------------------------
__global__ void __launch_bounds__(256) gather_pool_kernel(
        const float* __restrict__ image, float* __restrict__ out) {
    int blk  = blockIdx.x;
    int half = blk & 1;              // channel half: 0 -> c0..7, 1 -> c8..15
    int tile = (blk >> 1) & 255;     // 256 tiles per image
    int b    = blk >> 9;
    int i0 = (tile >> 2) * 4;        // pooled-row start (0..252)
    int j0 = (tile & 3) * 64;        // pooled-col start (0..192)

    __shared__ int sw[8][128];

    int tid = threadIdx.x;
    // stage 8x128 winner tile: one int4 per thread (8 rows x 32 int4)
    {
        int r  = tid >> 5;           // 0..7
        int c4 = tid & 31;           // 0..31
        const int4* wrow = (const int4*)(g_winner + (b << 18) + (2 * i0 + r) * WW + 2 * j0);
        *(int4*)&sw[r][c4 * 4] = wrow[c4];
    }
    __syncthreads();

    int li = tid >> 6;                    // 0..3  pooled row within tile
    int jj = tid & 63;                    // 0..63 pooled col within tile
    int w00 = sw[2 * li][2 * jj];
    int w01 = sw[2 * li][2 * jj + 1];
    int w10 = sw[2 * li + 1][2 * jj];
    int w11 = sw[2 * li + 1][2 * jj + 1];

    // clamped addresses (branchless); validity masks applied post-load
    int a00 = max(w00, 0), a01 = max(w01, 0);
    int a10 = max(w10, 0), a11 = max(w11, 0);

    int i2 = i0 + li;
    int j2 = j0 + jj;
    int opix = (2 * i2) * WW + 2 * j2;

    int cbase = half * 8;
#pragma unroll
    for (int cc = 0; cc < 8; cc += 4) {
        float v[16];
#pragma unroll
        for (int c = 0; c < 4; c++) {
            const float* img = image + ((unsigned)((b * NC + cbase + cc + c)) << 18);
            v[c * 4 + 0] = __ldg(img + a00);
            v[c * 4 + 1] = __ldg(img + a01);
            v[c * 4 + 2] = __ldg(img + a10);
            v[c * 4 + 3] = __ldg(img + a11);
        }
#pragma unroll
        for (int c = 0; c < 4; c++) {
            float b0 = (w00 >= 0) ? v[c * 4 + 0] : 0.0f;
            float b1 = (w01 >= 0) ? v[c * 4 + 1] : 0.0f;
            float b2 = (w10 >= 0) ? v[c * 4 + 2] : 0.0f;
            float b3 = (w11 >= 0) ? v[c * 4 + 3] : 0.0f;
            float m = fmaxf(fmaxf(b0, b1), fmaxf(b2, b3));

            float* o = out + ((unsigned)((b * NC + cbase + cc + c)) << 18) + opix;
            float2 vv = make_float2(m, m);
            __stcs((float2*)(o), vv);
            __stcs((float2*)(o + WW), vv);
        }
    }
}

// ---------------------------------------------------------------------------
// Launch: memset node (winner = -1), scatter, gather. Single stream,
// three graph nodes, nothing exotic.
// ---------------------------------------------------------------------------
extern "C" void kernel_launch(void* const* d_in, const int* in_sizes, int n_in,
                              void* d_out, int out_size) {
    const float* image = (const float*)d_in[0];   // [8,16,512,512]
    const float* depth = (const float*)d_in[1];   // [8,512,512]
    const float* T     = (const float*)d_in[2];   // [8,3,1]
    const float* R     = (const float*)d_in[3];   // [8,3,3]
    const float* K     = (const float*)d_in[4];   // [3,3]
    const float* Kinv  = (const float*)d_in[5];   // [3,3]
    float* out = (float*)d_out;

    void* winner_ptr = nullptr;
    cudaGetSymbolAddress(&winner_ptr, g_winner);
    cudaMemsetAsync(winner_ptr, 0xFF, (size_t)NB * HWN * sizeof(int), 0);

    scatter_kernel<<<(NB * HWN) / 256, 256>>>(depth, T, R, K, Kinv);
    gather_pool_kernel<<<NB * 512, 256>>>(image, out);
}

// round 15
// speedup vs baseline: 1.0505x; 1.0082x over previous
#include <cuda_runtime.h>
#include <cuda_bf16.h>

#define HH 512
#define WW 512
#define HWN (HH * WW)           // 262144 = 1<<18
#define NB 8
#define NC 16

// Scratch: scatter-winner per target pixel (largest source pixel index wins,
// matching sequential last-write-wins of the reference scatter).
__device__ int g_winner[NB * HWN];

// ---------------------------------------------------------------------------
// Projection + scatter, with M = (K @ R[b]) @ Kinv computed per block
// (thread 0, exact frozen chain -> smem). DO NOT TOUCH the arithmetic:
// rel_err == 0.0 with frcp_rn divide rewrites + gemm FMA x-chain + single-add.
// ---------------------------------------------------------------------------
__global__ void __launch_bounds__(256) scatter_kernel(
        const float* __restrict__ depth,      // already offset by b_off*HWN
        const float* __restrict__ T,
        const float* __restrict__ R,
        const float* __restrict__ K,
        const float* __restrict__ Kinv,
        int b_off) {
    __shared__ float sM[9];
    int lidx = blockIdx.x * 256 + threadIdx.x;   // 0 .. (nb_half*HWN)-1
    int b = (lidx >> 18) + b_off;                 // absolute batch
    int p = lidx & (HWN - 1);

    if (threadIdx.x == 0) {
        const float* Rb = R + b * 9;
        float KR[9];
#pragma unroll
        for (int i = 0; i < 3; i++) {
#pragma unroll
            for (int k = 0; k < 3; k++) {
                float s = __fmul_rn(K[i * 3 + 0], Rb[0 * 3 + k]);
                s = __fmaf_rn(K[i * 3 + 1], Rb[1 * 3 + k], s);
                s = __fmaf_rn(K[i * 3 + 2], Rb[2 * 3 + k], s);
                KR[i * 3 + k] = s;
            }
        }
#pragma unroll
        for (int i = 0; i < 3; i++) {
#pragma unroll
            for (int j = 0; j < 3; j++) {
                float s = __fmul_rn(KR[i * 3 + 0], Kinv[0 * 3 + j]);
                s = __fmaf_rn(KR[i * 3 + 1], Kinv[1 * 3 + j], s);
                s = __fmaf_rn(KR[i * 3 + 2], Kinv[2 * 3 + j], s);
                sM[i * 3 + j] = s;
            }
        }
    }
    __syncthreads();

    float gx = (float)(p >> 9);
    float gy = (float)(p & 511);

    float d = fmaxf(depth[lidx], 0.1f);

    float rd = __frcp_rn(d);
    float v0 = __fmul_rn(T[b * 3 + 0], rd);
    float v1 = __fmul_rn(T[b * 3 + 1], rd);
    float v2 = __fmul_rn(T[b * 3 + 2], rd);

    const float* M = sM;
    float x0 = __fadd_rn(__fmaf_rn(M[1], gy, __fmul_rn(M[0], gx)), M[2]);
    float x1 = __fadd_rn(__fmaf_rn(M[4], gy, __fmul_rn(M[3], gx)), M[5]);
    float x2 = __fadd_rn(__fmaf_rn(M[7], gy, __fmul_rn(M[6], gx)), M[8]);

    float y0 = __fmaf_rn(K[2], v2, __fmaf_rn(K[1], v1, __fmul_rn(K[0], v0)));
    float y1 = __fmaf_rn(K[5], v2, __fmaf_rn(K[4], v1, __fmul_rn(K[3], v0)));
    float y2 = __fmaf_rn(K[8], v2, __fmaf_rn(K[7], v1, __fmul_rn(K[6], v0)));

    float t0 = __fadd_rn(x0, y0);
    float t1 = __fadd_rn(x1, y1);
    float t2 = __fadd_rn(x2, y2);

    if (t0 == 0.0f) t0 = 1e-4f;
    if (t1 == 0.0f) t1 = 1e-4f;
    if (t2 == 0.0f) t2 = 1e-4f;

    float rt2 = __frcp_rn(t2);
    float u = __fmul_rn(t0, rt2);
    float v = __fmul_rn(t1, rt2);
    u = fminf(fmaxf(u, 0.0f), 511.0f);
    v = fminf(fmaxf(v, 0.0f), 511.0f);

    int q = ((int)u << 9) + (int)v;
    atomicMax(&g_winner[(b << 18) + q], p);
}

// ---------------------------------------------------------------------------
// Gather + maxpool(2x2) + nearest upsample(x2), fused.  [R14 structure]
// Block = 256 threads: one pooled tile (4 rows x 64 cols) x 8 channels.
// Two bursts of 16 outstanding gathers per thread. int4 winner staging,
// streaming (evict-first) output stores.
// ---------------------------------------------------------------------------
__global__ void __launch_bounds__(256) gather_pool_kernel(
        const float* __restrict__ image, float* __restrict__ out, int b_off) {
    int blk  = blockIdx.x;
    int half = blk & 1;              // channel half: 0 -> c0..7, 1 -> c8..15
    int tile = (blk >> 1) & 255;     // 256 tiles per image
    int b    = (blk >> 9) + b_off;
    int i0 = (tile >> 2) * 4;        // pooled-row start (0..252)
    int j0 = (tile & 3) * 64;        // pooled-col start (0..192)

    __shared__ int sw[8][128];

    int tid = threadIdx.x;
    // stage 8x128 winner tile: one int4 per thread (8 rows x 32 int4)
    {
        int r  = tid >> 5;           // 0..7
        int c4 = tid & 31;           // 0..31
        const int4* wrow = (const int4*)(g_winner + (b << 18) + (2 * i0 + r) * WW + 2 * j0);
        *(int4*)&sw[r][c4 * 4] = wrow[c4];
    }
    __syncthreads();

    int li = tid >> 6;                    // 0..3  pooled row within tile
    int jj = tid & 63;                    // 0..63 pooled col within tile
    int w00 = sw[2 * li][2 * jj];
    int w01 = sw[2 * li][2 * jj + 1];
    int w10 = sw[2 * li + 1][2 * jj];
    int w11 = sw[2 * li + 1][2 * jj + 1];

    // clamped addresses (branchless); validity masks applied post-load
    int a00 = max(w00, 0), a01 = max(w01, 0);
    int a10 = max(w10, 0), a11 = max(w11, 0);

    int i2 = i0 + li;
    int j2 = j0 + jj;
    int opix = (2 * i2) * WW + 2 * j2;

    int cbase = half * 8;
#pragma unroll
    for (int cc = 0; cc < 8; cc += 4) {
        float v[16];
#pragma unroll
        for (int c = 0; c < 4; c++) {
            const float* img = image + ((unsigned)((b * NC + cbase + cc + c)) << 18);
            v[c * 4 + 0] = __ldg(img + a00);
            v[c * 4 + 1] = __ldg(img + a01);
            v[c * 4 + 2] = __ldg(img + a10);
            v[c * 4 + 3] = __ldg(img + a11);
        }
#pragma unroll
        for (int c = 0; c < 4; c++) {
            float b0 = (w00 >= 0) ? v[c * 4 + 0] : 0.0f;
            float b1 = (w01 >= 0) ? v[c * 4 + 1] : 0.0f;
            float b2 = (w10 >= 0) ? v[c * 4 + 2] : 0.0f;
            float b3 = (w11 >= 0) ? v[c * 4 + 3] : 0.0f;
            float m = fmaxf(fmaxf(b0, b1), fmaxf(b2, b3));

            float* o = out + ((unsigned)((b * NC + cbase + cc + c)) << 18) + opix;
            float2 vv = make_float2(m, m);
            __stcs((float2*)(o), vv);
            __stcs((float2*)(o + WW), vv);
        }
    }
}

// ---------------------------------------------------------------------------
// Launch: two independent batch halves on two streams, each half running
// memset -> scatter -> gather. Stream/events created once on the first
// (uncaptured) correctness call; the captured graph uses the documented
// event fork/join pattern.
// ---------------------------------------------------------------------------
extern "C" void kernel_launch(void* const* d_in, const int* in_sizes, int n_in,
                              void* d_out, int out_size) {
    const float* image = (const float*)d_in[0];   // [8,16,512,512]
    const float* depth = (const float*)d_in[1];   // [8,512,512]
    const float* T     = (const float*)d_in[2];   // [8,3,1]
    const float* R     = (const float*)d_in[3];   // [8,3,3]
    const float* K     = (const float*)d_in[4];   // [3,3]
    const float* Kinv  = (const float*)d_in[5];   // [3,3]
    float* out = (float*)d_out;

    static cudaStream_t s2 = nullptr;
    static cudaEvent_t e_fork = nullptr, e_join = nullptr;
    if (s2 == nullptr) {
        cudaStreamCreateWithFlags(&s2, cudaStreamNonBlocking);
        cudaEventCreateWithFlags(&e_fork, cudaEventDisableTiming);
        cudaEventCreateWithFlags(&e_join, cudaEventDisableTiming);
    }

    void* winner_ptr = nullptr;
    cudaGetSymbolAddress(&winner_ptr, g_winner);

    const int NBH = NB / 2;                       // 4 batches per half
    const size_t halfBytes = (size_t)NBH * HWN * sizeof(int);

    // fork s2 from the capture-origin stream before any work
    cudaEventRecord(e_fork, 0);
    cudaStreamWaitEvent(s2, e_fork, 0);

    // half 1 on origin stream (batches 0..3)
    cudaMemsetAsync(winner_ptr, 0xFF, halfBytes, 0);
    scatter_kernel<<<(NBH * HWN) / 256, 256>>>(depth, T, R, K, Kinv, 0);
    gather_pool_kernel<<<NBH * 512, 256>>>(image, out, 0);

    // half 2 on s2 (batches 4..7)
    cudaMemsetAsync((char*)winner_ptr + halfBytes, 0xFF, halfBytes, s2);
    scatter_kernel<<<(NBH * HWN) / 256, 256, 0, s2>>>(
        depth + ((size_t)NBH << 18), T, R, K, Kinv, NBH);
    gather_pool_kernel<<<NBH * 512, 256, 0, s2>>>(image, out, NBH);

    // join s2 back into the origin stream
    cudaEventRecord(e_join, s2);
    cudaStreamWaitEvent(0, e_join, 0);
}